// round 9
// baseline (speedup 1.0000x reference)
#include <cuda_runtime.h>
#include <cstdint>

// Temporal_Attention — weight-space-collapsed.
// k_pre: weight-only precompute (G', ub', gb', dq', M, cbias, S).
// k_main: per-batch cluster of 2 CTAs (t-halves), 512 thr, single wave,
//         launched with PDL so phase 0 overlaps k_pre.
// B=64, T=256, D=128, H=8, E=128.  out[B,D] fp32.

#define BB 64
#define TT 256
#define DD 128
#define HH 8
#define HE 1024
#define SCALE 0.088388347648318447f

static __device__ float g_S;
static __device__ __align__(16) float g_G[HH * DD * DD];   // [h][dp][d]
static __device__ __align__(16) float g_ub[HH * DD];
static __device__ __align__(16) float g_gb[HH * DD];
static __device__ float g_dqs[HH];
static __device__ __align__(16) float g_M[HE * DD];        // [k][d2]
static __device__ __align__(16) float g_cbp[8 * DD];

// ---- helpers ---------------------------------------------------------------
__device__ __forceinline__ void ffma2(unsigned long long& d,
                                      unsigned long long a, unsigned long long b) {
    asm("fma.rn.f32x2 %0, %1, %2, %0;" : "+l"(d) : "l"(a), "l"(b));
}
__device__ __forceinline__ unsigned long long pk2(float x, float y) {
    unsigned long long r;
    asm("mov.b64 %0, {%1, %2};" : "=l"(r) : "f"(x), "f"(y));
    return r;
}
__device__ __forceinline__ float2 upk2(unsigned long long v) {
    float lo, hi;
    asm("mov.b64 {%0, %1}, %2;" : "=f"(lo), "=f"(hi) : "l"(v));
    return make_float2(lo, hi);
}
__device__ __forceinline__ float dot4(float4 a, float4 b) {
    return a.x * b.x + a.y * b.y + a.z * b.z + a.w * b.w;
}
__device__ __forceinline__ uint32_t smem_u32(const void* p) {
    uint32_t a;
    asm("{ .reg .u64 t; cvta.to.shared.u64 t, %1; cvt.u32.u64 %0, t; }"
        : "=r"(a) : "l"(p));
    return a;
}
__device__ __forceinline__ uint32_t mapa_rank(uint32_t addr, uint32_t rank) {
    uint32_t r;
    asm("mapa.shared::cluster.u32 %0, %1, %2;" : "=r"(r) : "r"(addr), "r"(rank));
    return r;
}
__device__ __forceinline__ float ld_dsmem(uint32_t a) {
    float v;
    asm volatile("ld.shared::cluster.f32 %0, [%1];" : "=f"(v) : "r"(a));
    return v;
}
#define CLUSTER_SYNC() do { \
    asm volatile("barrier.cluster.arrive.aligned;" ::: "memory"); \
    asm volatile("barrier.cluster.wait.aligned;" ::: "memory"); \
} while (0)
#define CLUSTER_ARRIVE() asm volatile("barrier.cluster.arrive.aligned;" ::: "memory")
#define CLUSTER_WAIT()   asm volatile("barrier.cluster.wait.aligned;" ::: "memory")

// ===========================================================================
// K1: grid 145 x 256.  roles: G(0-63) | M(64-127) | gb(128-135)
//                             | cbias(136-143) | misc(144)
__global__ __launch_bounds__(256) void k_pre(
    const float* __restrict__ Ws,
    const float* __restrict__ Wk, const float* __restrict__ bk,
    const float* __restrict__ Wq, const float* __restrict__ bq,
    const float* __restrict__ Wv, const float* __restrict__ bv,
    const float* __restrict__ Wo, const float* __restrict__ bo)
{
    __shared__ __align__(16) float s[12288];   // 48 KB
    const int blk = blockIdx.x, tid = threadIdx.x;

    if (blk < 64) {
        // ------------- G role: G'[h, r0..r0+15, :] (+ub on rt==0) -------------
        const int w = blk, h = w >> 3, rt = w & 7, r0 = rt * 16;
        const int d2 = tid & 127, rg = tid >> 7;
        float4* wq4s = (float4*)s;            // [128][17] float4
        float4* wk4s = (float4*)(s + 8704);   // [16][16]
        float4* bk4s = (float4*)(s + 9728);   // [16]
        const float4* Wq4 = (const float4*)Wq;
        const float4* Wk4 = (const float4*)Wk;
        float acc[8];
        #pragma unroll
        for (int j = 0; j < 8; j++) acc[j] = 0.f;
        float ubacc = 0.f;
        for (int e0 = 0; e0 < 2; e0++) {           // e-chunks of 64
            #pragma unroll
            for (int k = 0; k < 8; k++) {
                int i = tid + k * 256;
                int dd = i >> 4, eq = i & 15;
                wq4s[dd * 17 + eq] = Wq4[dd * 256 + h * 32 + e0 * 16 + eq];
            }
            {
                int r = tid >> 4, eq = tid & 15;
                wk4s[r * 16 + eq] = Wk4[(r0 + r) * 256 + h * 32 + e0 * 16 + eq];
            }
            if (rt == 0 && tid < 16)
                bk4s[tid] = ((const float4*)bk)[h * 32 + e0 * 16 + tid];
            __syncthreads();
            #pragma unroll 4
            for (int e4 = 0; e4 < 16; e4++) {
                float4 q4 = wq4s[d2 * 17 + e4];
                #pragma unroll
                for (int j = 0; j < 8; j++)
                    acc[j] += dot4(q4, wk4s[(rg * 8 + j) * 16 + e4]);
                if (rt == 0 && rg == 0) ubacc += dot4(q4, bk4s[e4]);
            }
            __syncthreads();
        }
        #pragma unroll
        for (int j = 0; j < 8; j++)
            g_G[h * 16384 + (r0 + rg * 8 + j) * DD + d2] = SCALE * acc[j];
        if (rt == 0 && rg == 0) g_ub[h * DD + d2] = SCALE * ubacc;
    } else if (blk < 128) {
        // ------------- M role: M[h, r0..r0+15, :] -------------
        const int w = blk - 64, h = w >> 3, r0 = (w & 7) * 16;
        const int d2 = tid & 127, rh = tid >> 7;
        float* wo_s = s;            // 64 x 128
        float* wv_s = s + 8192;     // 16 x 64
        float acc[8];
        #pragma unroll
        for (int j = 0; j < 8; j++) acc[j] = 0.f;
        for (int e0 = 0; e0 < 128; e0 += 64) {
            for (int i = tid; i < 8192; i += 256) {
                int e = i >> 7, dd = i & 127;
                wo_s[i] = Wo[(h * 128 + e0 + e) * DD + dd];
            }
            for (int i = tid; i < 1024; i += 256) {
                int r = i >> 6, e = i & 63;
                wv_s[i] = Wv[(r0 + r) * HE + h * 128 + e0 + e];
            }
            __syncthreads();
            #pragma unroll 8
            for (int e = 0; e < 64; e++) {
                float wo = wo_s[e * 128 + d2];
                #pragma unroll
                for (int j = 0; j < 8; j++)
                    acc[j] += wv_s[(rh * 8 + j) * 64 + e] * wo;
            }
            __syncthreads();
        }
        #pragma unroll
        for (int j = 0; j < 8; j++)
            g_M[(h * 128 + r0 + rh * 8 + j) * DD + d2] = acc[j];
    } else if (blk < 136) {
        // ------------- gb role: gb'[h, :] -------------
        const int h = blk - 128, eq = tid & 31, dg = tid >> 5;
        float4 bqv = ((const float4*)bq)[h * 32 + eq];
        const float4* Wk4 = (const float4*)Wk;
        #pragma unroll
        for (int i = 0; i < 16; i++) {
            int dd = dg * 16 + i;
            float p = dot4(Wk4[dd * 256 + h * 32 + eq], bqv);
            #pragma unroll
            for (int o = 16; o > 0; o >>= 1)
                p += __shfl_xor_sync(0xffffffffu, p, o);
            if (eq == 0) g_gb[h * DD + dd] = SCALE * p;
        }
    } else if (blk < 144) {
        // ------------- cbias partial: k-slice p -------------
        const int p = blk - 136, d2 = tid & 127, kh = tid >> 7;
        float acc = 0.f;
        #pragma unroll 8
        for (int i = 0; i < 64; i++) {
            int k = p * 128 + kh * 64 + i;
            acc += __ldg(bv + k) * Wo[k * DD + d2];
        }
        s[tid] = acc;
        __syncthreads();
        if (kh == 0)
            g_cbp[p * DD + d2] = s[d2] + s[128 + d2] + (p == 0 ? bo[d2] : 0.f);
    } else {
        // ------------- misc: S, dq' -------------
        s[tid] = Ws[tid];
        {
            int h = tid >> 5, lane = tid & 31;
            float p = dot4(((const float4*)bk)[h * 32 + lane],
                           ((const float4*)bq)[h * 32 + lane]);
            #pragma unroll
            for (int o = 16; o > 0; o >>= 1)
                p += __shfl_xor_sync(0xffffffffu, p, o);
            if (lane == 0) g_dqs[h] = SCALE * p;
        }
        __syncthreads();
        for (int st = 128; st > 0; st >>= 1) {
            if (tid < st) s[tid] += s[tid + st];
            __syncthreads();
        }
        if (tid == 0) g_S = s[0];
    }
}

// ===========================================================================
// K2: cluster of 2 CTAs per batch, each owns a t-half (128 t).
//   grid 128 x 512 thr, dynamic smem ~98 KB.  Single wave.
//
// smem float offsets:
#define SX_PAD  132
#define OSX   0        // sx [128 t][132 d pad]  16896
#define OWS   16896    // Ws half                128
#define OXSP  17024    // xs partial             128
#define OXSF  17152    // xs full                128
#define OSU   17280    // u  [128 d][8 h]        1024
#define OSC   18304    // c[8]                   8
#define OBETA 18312    // beta [128 t][8 h]      1024
#define OMAX  19336    // 8
#define OSUM  19344    // 8
#define OSF   19352    // 8
#define OPART 19360    // scratch                4096
#define OYOWN 23456    // y own t-partial        1024
#define OYQ   24480    // y full, own k-half     512
#define OOUT  24992    // out partial, all cols  128
#define K2_FLOATS 25120

extern "C" __global__ __launch_bounds__(512, 1) __cluster_dims__(2, 1, 1)
void k_main(const float* __restrict__ x, const float* __restrict__ Ws,
            const float* __restrict__ bs, float* __restrict__ out)
{
    extern __shared__ __align__(16) float sm[];
    float* sx    = sm + OSX;
    float* sWs   = sm + OWS;
    float* xs_p  = sm + OXSP;
    float* xs_f  = sm + OXSF;
    float* su    = sm + OSU;
    float* sc    = sm + OSC;
    float* sbeta = sm + OBETA;
    float* smax_ = sm + OMAX;
    float* ssum_ = sm + OSUM;
    float* sf    = sm + OSF;
    float* spart = sm + OPART;
    float* syown = sm + OYOWN;
    float* syq   = sm + OYQ;
    float* sout  = sm + OOUT;

    const int tid = threadIdx.x;
    uint32_t rank;
    asm("mov.u32 %0, %%cluster_ctarank;" : "=r"(rank));
    const int r = (int)rank;
    const uint32_t peer = 1u - rank;
    const int b = blockIdx.x >> 1;

    // ---- phase 0 (overlaps k_pre under PDL): fill x tile [t][d] + xs partial
    if (tid < 128) sWs[tid] = Ws[r * 128 + tid];
    __syncthreads();
    {
        const int d = tid & 127, tg = tid >> 7;   // 4 t-groups
        const float* xb = x + ((size_t)(b * TT + r * 128)) * DD + d;
        float acc = 0.f;
        #pragma unroll
        for (int k = 0; k < 32; k++) {
            int t = k * 4 + tg;
            float v = xb[t * DD];
            sx[t * SX_PAD + d] = v;
            acc += sWs[t] * v;
        }
        spart[tg * 128 + d] = acc;
    }
    __syncthreads();
    if (tid < 128)
        xs_p[tid] = spart[tid] + spart[128 + tid] + spart[256 + tid] + spart[384 + tid];

    // wait for k_pre results (G, ub, gb, dqs, S, M, cbp) before any use
    cudaGridDependencySynchronize();
    CLUSTER_SYNC();   // #1: xs partials visible

    // ---- phase 1: xs full, u own d-half (float4 G loads), c[h] ----
    if (tid < 128) {
        uint32_t la = smem_u32(xs_p + tid);
        xs_f[tid] = xs_p[tid] + ld_dsmem(mapa_rank(la, peer));
    }
    __syncthreads();
    {   // thread: h = tid>>6, f4 = (tid>>2)&15 (16 f4 = own 64 d), strip = tid&3
        const int h = tid >> 6, f4 = (tid >> 2) & 15, strip = tid & 3;
        const float4* G4 = (const float4*)g_G + h * 4096 + r * 16 + f4;
        float4 acc = make_float4(0.f, 0.f, 0.f, 0.f);
        #pragma unroll
        for (int i = 0; i < 32; i++) {
            int dp = strip * 32 + i;
            float xv = xs_f[dp];
            float4 gv = G4[dp * 32];
            acc.x += xv * gv.x; acc.y += xv * gv.y;
            acc.z += xv * gv.z; acc.w += xv * gv.w;
        }
        ((float4*)spart)[(h * 16 + f4) * 4 + strip] = acc;
    }
    __syncthreads();
    {   // reduce strips -> su[d*8+h] (+ S*ub)
        const int h = tid >> 6, f4 = (tid >> 2) & 15, comp = tid & 3;
        const int base = ((h * 16 + f4) * 4) * 4 + comp;
        float v = spart[base] + spart[base + 4] + spart[base + 8] + spart[base + 12];
        const int d = r * 64 + f4 * 4 + comp;
        su[d * 8 + h] = v + g_S * g_ub[h * 128 + d];
    }
    __syncthreads();
    CLUSTER_ARRIVE();   // #2 arrive — peers may read su after their wait
    if (tid < 256) {    // c[h] in barrier shadow (CTA-local)
        int h = tid >> 5, lane = tid & 31;
        float p = dot4(((const float4*)xs_f)[lane],
                       ((const float4*)g_gb)[h * 32 + lane]);
        #pragma unroll
        for (int o = 16; o > 0; o >>= 1)
            p += __shfl_xor_sync(0xffffffffu, p, o);
        if (lane == 0) sc[h] = p + g_S * g_dqs[h] + bs[0];
    }
    CLUSTER_WAIT();     // #2 wait

    // ---- phase 2: gather peer u half; summary over own t-half ----
    {   // peer's 64 d -> su offsets [peer*512, peer*512+512)
        int off = (int)peer * 512 + tid;
        su[off] = ld_dsmem(mapa_rank(smem_u32(su + off), peer));
    }
    __syncthreads();
    {   // thread = (t = tid&127, dq = tid>>7 of 4): x row chunk in registers
        const int t = tid & 127, dq = tid >> 7;
        float xr[32];
        const float4* xrow = (const float4*)(sx + t * SX_PAD + dq * 32);
        #pragma unroll
        for (int i = 0; i < 8; i++) {
            float4 v = xrow[i];
            xr[i * 4 + 0] = v.x; xr[i * 4 + 1] = v.y;
            xr[i * 4 + 2] = v.z; xr[i * 4 + 3] = v.w;
        }
        unsigned long long a0 = 0, a1 = 0, a2 = 0, a3 = 0;
        #pragma unroll
        for (int i = 0; i < 32; i++) {
            int d = dq * 32 + i;
            unsigned long long xp = pk2(xr[i], xr[i]);
            const unsigned long long* up = (const unsigned long long*)(su + d * 8);
            ffma2(a0, up[0], xp); ffma2(a1, up[1], xp);
            ffma2(a2, up[2], xp); ffma2(a3, up[3], xp);
        }
        float2 f0 = upk2(a0), f1 = upk2(a1), f2 = upk2(a2), f3 = upk2(a3);
        ((float4*)spart)[(t * 4 + dq) * 2 + 0] = make_float4(f0.x, f0.y, f1.x, f1.y);
        ((float4*)spart)[(t * 4 + dq) * 2 + 1] = make_float4(f2.x, f2.y, f3.x, f3.y);
    }
    __syncthreads();
    #pragma unroll
    for (int k = 0; k < 2; k++) {
        int i = tid + k * 512;            // i = t*8 + h
        int t = i >> 3, h = i & 7;
        sbeta[i] = spart[(t * 4 + 0) * 8 + h] + spart[(t * 4 + 1) * 8 + h]
                 + spart[(t * 4 + 2) * 8 + h] + spart[(t * 4 + 3) * 8 + h] + sc[h];
    }
    __syncthreads();

    // ---- phase 3: own-half softmax stats; sbeta <- e^{v-m_own} ----
    if (tid < 256) {
        int h = tid >> 5, lane = tid & 31;
        float v[4];
        float m = -1e30f;
        #pragma unroll
        for (int i = 0; i < 4; i++) {
            v[i] = sbeta[(lane + 32 * i) * 8 + h];
            m = fmaxf(m, v[i]);
        }
        #pragma unroll
        for (int o = 16; o > 0; o >>= 1)
            m = fmaxf(m, __shfl_xor_sync(0xffffffffu, m, o));
        float ss = 0.f;
        #pragma unroll
        for (int i = 0; i < 4; i++) { v[i] = __expf(v[i] - m); ss += v[i]; }
        #pragma unroll
        for (int o = 16; o > 0; o >>= 1)
            ss += __shfl_xor_sync(0xffffffffu, ss, o);
        #pragma unroll
        for (int i = 0; i < 4; i++) sbeta[(lane + 32 * i) * 8 + h] = v[i];
        if (lane == 0) { smax_[h] = m; ssum_[h] = ss; }
    }
    CLUSTER_SYNC();   // #3
    if (tid < 8) {
        float mo = smax_[tid], so = ssum_[tid];
        float mp = ld_dsmem(mapa_rank(smem_u32(smax_ + tid), peer));
        float sp = ld_dsmem(mapa_rank(smem_u32(ssum_ + tid), peer));
        float m = fmaxf(mo, mp);
        float denom = so * __expf(mo - m) + sp * __expf(mp - m);
        sf[tid] = __expf(mo - m) / denom;
    }
    __syncthreads();

    // ---- phase 4: y own t-half partial (renorm via sf) ----
    {
        const int d = tid & 127, tg = tid >> 7;   // 4 t-groups of 32
        unsigned long long a0 = 0, a1 = 0, a2 = 0, a3 = 0;
        #pragma unroll 8
        for (int i = 0; i < 32; i++) {
            int t = tg * 32 + i;
            float xv = sx[t * SX_PAD + d];
            unsigned long long xp = pk2(xv, xv);
            const ulonglong2* bp = (const ulonglong2*)(sbeta + t * 8);
            ulonglong2 b01 = bp[0], b23 = bp[1];
            ffma2(a0, b01.x, xp); ffma2(a1, b01.y, xp);
            ffma2(a2, b23.x, xp); ffma2(a3, b23.y, xp);
        }
        float2 v0 = upk2(a0), v1 = upk2(a1), v2 = upk2(a2), v3 = upk2(a3);
        float* pg = spart + tg * 1024;
        pg[0 * 128 + d] = v0.x; pg[1 * 128 + d] = v0.y;
        pg[2 * 128 + d] = v1.x; pg[3 * 128 + d] = v1.y;
        pg[4 * 128 + d] = v2.x; pg[5 * 128 + d] = v2.y;
        pg[6 * 128 + d] = v3.x; pg[7 * 128 + d] = v3.y;
    }
    __syncthreads();
    #pragma unroll
    for (int k = 0; k < 2; k++) {
        int i = tid + k * 512;            // i = h*128 + d
        syown[i] = sf[i >> 7] *
            (spart[i] + spart[1024 + i] + spart[2048 + i] + spart[3072 + i]);
    }
    CLUSTER_SYNC();   // #4

    // ---- phase 5: y full own k-half; out partial for ALL 128 cols ----
    {
        int k = r * 512 + tid;
        syq[tid] = syown[k] + ld_dsmem(mapa_rank(smem_u32(syown + k), peer));
    }
    __syncthreads();
    {   // thread: f4 = tid&31 (32 f4 = 128 cols), kg = tid>>5 (16 groups of 32 k)
        const int f4 = tid & 31, kg = tid >> 5;
        const float4* M4 = (const float4*)g_M + (r * 512 + kg * 32) * 32 + f4;
        float4 acc = make_float4(0.f, 0.f, 0.f, 0.f);
        #pragma unroll
        for (int kk = 0; kk < 32; kk++) {
            float yk = syq[kg * 32 + kk];
            float4 mv = M4[kk * 32];
            acc.x += yk * mv.x; acc.y += yk * mv.y;
            acc.z += yk * mv.z; acc.w += yk * mv.w;
        }
        ((float4*)spart)[kg * 32 + f4] = acc;
    }
    __syncthreads();
    if (tid < 128) {
        float v = 0.f;
        #pragma unroll
        for (int kg = 0; kg < 16; kg++) v += spart[kg * 128 + tid];
        sout[tid] = v;
    }
    CLUSTER_SYNC();   // #5
    if (tid < 64) {
        int c = r * 64 + tid;
        float o = 0.f;
        #pragma unroll
        for (int p = 0; p < 8; p++) o += g_cbp[p * DD + c];
        o += sout[c] + ld_dsmem(mapa_rank(smem_u32(sout + c), peer));
        out[b * DD + c] = o;
    }
    CLUSTER_SYNC();   // #6: exit guard
}

// ===========================================================================
extern "C" void kernel_launch(void* const* d_in, const int* in_sizes, int n_in,
                              void* d_out, int out_size) {
    const float* x  = (const float*)d_in[0];
    const float* Wq = (const float*)d_in[1];
    const float* bq = (const float*)d_in[2];
    const float* Wk = (const float*)d_in[3];
    const float* bk = (const float*)d_in[4];
    const float* Wv = (const float*)d_in[5];
    const float* bv = (const float*)d_in[6];
    const float* Ws = (const float*)d_in[7];
    const float* bs = (const float*)d_in[8];
    const float* Wo = (const float*)d_in[9];
    const float* bo = (const float*)d_in[10];
    float* out = (float*)d_out;

    static bool attr_done = false;
    if (!attr_done) {
        cudaFuncSetAttribute(k_main, cudaFuncAttributeMaxDynamicSharedMemorySize,
                             K2_FLOATS * 4);
        attr_done = true;
    }

    k_pre<<<145, 256>>>(Ws, Wk, bk, Wq, bq, Wv, bv, Wo, bo);

    // k_main with PDL: phase 0 (x fill) overlaps k_pre; gridDepSync gates G/M use.
    cudaLaunchConfig_t cfg = {};
    cfg.gridDim = dim3(128, 1, 1);
    cfg.blockDim = dim3(512, 1, 1);
    cfg.dynamicSmemBytes = K2_FLOATS * 4;
    cfg.stream = 0;
    cudaLaunchAttribute attrs[1];
    attrs[0].id = cudaLaunchAttributeProgrammaticStreamSerialization;
    attrs[0].val.programmaticStreamSerializationAllowed = 1;
    cfg.attrs = attrs;
    cfg.numAttrs = 1;
    cudaLaunchKernelEx(&cfg, k_main, x, Ws, bs, out);
}

// round 10
// speedup vs baseline: 1.2564x; 1.2564x over previous
#include <cuda_runtime.h>
#include <cstdint>

// Temporal_Attention — weight-space-collapsed.
// k_pre: weight-only precompute (G', ub', gb', dq', M, cbias, S); triggers
//        programmatic launch completion at entry so k_main overlaps it.
// k_main: per-batch cluster of 4 CTAs (t-quarters), 256 thr, 55 KB smem
//         (2 CTAs/SM co-resident, single wave). PDL: phase 0 + xs exchange
//         run concurrently with k_pre; gridDepSync gates first G/S use.
// B=64, T=256, D=128, H=8, E=128.  out[B,D] fp32.

#define BB 64
#define TT 256
#define DD 128
#define HH 8
#define HE 1024
#define SCALE 0.088388347648318447f

static __device__ float g_S;
static __device__ __align__(16) float g_G[HH * DD * DD];   // [h][dp][d]
static __device__ __align__(16) float g_ub[HH * DD];
static __device__ __align__(16) float g_gb[HH * DD];
static __device__ float g_dqs[HH];
static __device__ __align__(16) float g_M[HE * DD];        // [k][d2]
static __device__ __align__(16) float g_cbp[8 * DD];

// ---- helpers ---------------------------------------------------------------
__device__ __forceinline__ void ffma2(unsigned long long& d,
                                      unsigned long long a, unsigned long long b) {
    asm("fma.rn.f32x2 %0, %1, %2, %0;" : "+l"(d) : "l"(a), "l"(b));
}
__device__ __forceinline__ unsigned long long pk2(float x, float y) {
    unsigned long long r;
    asm("mov.b64 %0, {%1, %2};" : "=l"(r) : "f"(x), "f"(y));
    return r;
}
__device__ __forceinline__ float2 upk2(unsigned long long v) {
    float lo, hi;
    asm("mov.b64 {%0, %1}, %2;" : "=f"(lo), "=f"(hi) : "l"(v));
    return make_float2(lo, hi);
}
__device__ __forceinline__ float dot4(float4 a, float4 b) {
    return a.x * b.x + a.y * b.y + a.z * b.z + a.w * b.w;
}
__device__ __forceinline__ uint32_t smem_u32(const void* p) {
    uint32_t a;
    asm("{ .reg .u64 t; cvta.to.shared.u64 t, %1; cvt.u32.u64 %0, t; }"
        : "=r"(a) : "l"(p));
    return a;
}
__device__ __forceinline__ uint32_t mapa_rank(uint32_t addr, uint32_t rank) {
    uint32_t r;
    asm("mapa.shared::cluster.u32 %0, %1, %2;" : "=r"(r) : "r"(addr), "r"(rank));
    return r;
}
__device__ __forceinline__ float ld_dsmem(uint32_t a) {
    float v;
    asm volatile("ld.shared::cluster.f32 %0, [%1];" : "=f"(v) : "r"(a));
    return v;
}
#define CLUSTER_SYNC() do { \
    asm volatile("barrier.cluster.arrive.aligned;" ::: "memory"); \
    asm volatile("barrier.cluster.wait.aligned;" ::: "memory"); \
} while (0)
#define CLUSTER_ARRIVE() asm volatile("barrier.cluster.arrive.aligned;" ::: "memory")
#define CLUSTER_WAIT()   asm volatile("barrier.cluster.wait.aligned;" ::: "memory")

// ===========================================================================
// K1: grid 145 x 256.  roles: G(0-63) | M(64-127) | gb(128-135)
//                             | cbias(136-143) | misc(144)
__global__ __launch_bounds__(256) void k_pre(
    const float* __restrict__ Ws,
    const float* __restrict__ Wk, const float* __restrict__ bk,
    const float* __restrict__ Wq, const float* __restrict__ bq,
    const float* __restrict__ Wv, const float* __restrict__ bv,
    const float* __restrict__ Wo, const float* __restrict__ bo)
{
    // Fire the PDL trigger immediately: grid (145) fits one wave, so the
    // dependent k_main launch starts while k_pre is still computing.
    cudaTriggerProgrammaticLaunchCompletion();

    __shared__ __align__(16) float s[12288];   // 48 KB
    const int blk = blockIdx.x, tid = threadIdx.x;

    if (blk < 64) {
        // ------------- G role: G'[h, r0..r0+15, :] (+ub on rt==0) -------------
        const int w = blk, h = w >> 3, rt = w & 7, r0 = rt * 16;
        const int d2 = tid & 127, rg = tid >> 7;
        float4* wq4s = (float4*)s;            // [128][17] float4
        float4* wk4s = (float4*)(s + 8704);   // [16][16]
        float4* bk4s = (float4*)(s + 9728);   // [16]
        const float4* Wq4 = (const float4*)Wq;
        const float4* Wk4 = (const float4*)Wk;
        float acc[8];
        #pragma unroll
        for (int j = 0; j < 8; j++) acc[j] = 0.f;
        float ubacc = 0.f;
        for (int e0 = 0; e0 < 2; e0++) {           // e-chunks of 64
            #pragma unroll
            for (int k = 0; k < 8; k++) {
                int i = tid + k * 256;
                int dd = i >> 4, eq = i & 15;
                wq4s[dd * 17 + eq] = Wq4[dd * 256 + h * 32 + e0 * 16 + eq];
            }
            {
                int r = tid >> 4, eq = tid & 15;
                wk4s[r * 16 + eq] = Wk4[(r0 + r) * 256 + h * 32 + e0 * 16 + eq];
            }
            if (rt == 0 && tid < 16)
                bk4s[tid] = ((const float4*)bk)[h * 32 + e0 * 16 + tid];
            __syncthreads();
            #pragma unroll 4
            for (int e4 = 0; e4 < 16; e4++) {
                float4 q4 = wq4s[d2 * 17 + e4];
                #pragma unroll
                for (int j = 0; j < 8; j++)
                    acc[j] += dot4(q4, wk4s[(rg * 8 + j) * 16 + e4]);
                if (rt == 0 && rg == 0) ubacc += dot4(q4, bk4s[e4]);
            }
            __syncthreads();
        }
        #pragma unroll
        for (int j = 0; j < 8; j++)
            g_G[h * 16384 + (r0 + rg * 8 + j) * DD + d2] = SCALE * acc[j];
        if (rt == 0 && rg == 0) g_ub[h * DD + d2] = SCALE * ubacc;
    } else if (blk < 128) {
        // ------------- M role: M[h, r0..r0+15, :] -------------
        const int w = blk - 64, h = w >> 3, r0 = (w & 7) * 16;
        const int d2 = tid & 127, rh = tid >> 7;
        float* wo_s = s;            // 64 x 128
        float* wv_s = s + 8192;     // 16 x 64
        float acc[8];
        #pragma unroll
        for (int j = 0; j < 8; j++) acc[j] = 0.f;
        for (int e0 = 0; e0 < 128; e0 += 64) {
            for (int i = tid; i < 8192; i += 256) {
                int e = i >> 7, dd = i & 127;
                wo_s[i] = Wo[(h * 128 + e0 + e) * DD + dd];
            }
            for (int i = tid; i < 1024; i += 256) {
                int r = i >> 6, e = i & 63;
                wv_s[i] = Wv[(r0 + r) * HE + h * 128 + e0 + e];
            }
            __syncthreads();
            #pragma unroll 8
            for (int e = 0; e < 64; e++) {
                float wo = wo_s[e * 128 + d2];
                #pragma unroll
                for (int j = 0; j < 8; j++)
                    acc[j] += wv_s[(rh * 8 + j) * 64 + e] * wo;
            }
            __syncthreads();
        }
        #pragma unroll
        for (int j = 0; j < 8; j++)
            g_M[(h * 128 + r0 + rh * 8 + j) * DD + d2] = acc[j];
    } else if (blk < 136) {
        // ------------- gb role: gb'[h, :] -------------
        const int h = blk - 128, eq = tid & 31, dg = tid >> 5;
        float4 bqv = ((const float4*)bq)[h * 32 + eq];
        const float4* Wk4 = (const float4*)Wk;
        #pragma unroll
        for (int i = 0; i < 16; i++) {
            int dd = dg * 16 + i;
            float p = dot4(Wk4[dd * 256 + h * 32 + eq], bqv);
            #pragma unroll
            for (int o = 16; o > 0; o >>= 1)
                p += __shfl_xor_sync(0xffffffffu, p, o);
            if (eq == 0) g_gb[h * DD + dd] = SCALE * p;
        }
    } else if (blk < 144) {
        // ------------- cbias partial: k-slice p -------------
        const int p = blk - 136, d2 = tid & 127, kh = tid >> 7;
        float acc = 0.f;
        #pragma unroll 8
        for (int i = 0; i < 64; i++) {
            int k = p * 128 + kh * 64 + i;
            acc += __ldg(bv + k) * Wo[k * DD + d2];
        }
        s[tid] = acc;
        __syncthreads();
        if (kh == 0)
            g_cbp[p * DD + d2] = s[d2] + s[128 + d2] + (p == 0 ? bo[d2] : 0.f);
    } else {
        // ------------- misc: S, dq' -------------
        s[tid] = Ws[tid];
        {
            int h = tid >> 5, lane = tid & 31;
            float p = dot4(((const float4*)bk)[h * 32 + lane],
                           ((const float4*)bq)[h * 32 + lane]);
            #pragma unroll
            for (int o = 16; o > 0; o >>= 1)
                p += __shfl_xor_sync(0xffffffffu, p, o);
            if (lane == 0) g_dqs[h] = SCALE * p;
        }
        __syncthreads();
        for (int st = 128; st > 0; st >>= 1) {
            if (tid < st) s[tid] += s[tid + st];
            __syncthreads();
        }
        if (tid == 0) g_S = s[0];
    }
}

// ===========================================================================
// K2: cluster of 4 CTAs per batch, each owns a t-quarter (64 t).
//   grid 256 x 256 thr, dynamic smem 55.2 KB (2 CTAs/SM co-resident).
//
// smem float offsets:
#define SX_PAD  132
#define OSX   0        // sx [64 t][132 d pad]   8448
#define OWS   8448     // Ws quarter             64
#define OXSP  8512     // xs partial             128
#define OXSF  8640     // xs full                128
#define OSU   8768     // u  [128 d][8 h]        1024
#define OSC   9792     // c[8]                   8
#define OBETA 9800     // beta [64 t][8 h]       512
#define OMAX  10312    // 8
#define OSUM  10320    // 8
#define OSF   10328    // 8
#define OPART 10336    // scratch                2048
#define OYOWN 12384    // y own t-partial        1024
#define OYQ   13408    // y full, own k-quarter  256
#define OOUT  13664    // out partial            128
#define K2_FLOATS 13792

extern "C" __global__ __launch_bounds__(256, 2) __cluster_dims__(4, 1, 1)
void k_main(const float* __restrict__ x, const float* __restrict__ Ws,
            const float* __restrict__ bs, float* __restrict__ out)
{
    extern __shared__ __align__(16) float sm[];
    float* sx    = sm + OSX;
    float* sWs   = sm + OWS;
    float* xs_p  = sm + OXSP;
    float* xs_f  = sm + OXSF;
    float* su    = sm + OSU;
    float* sc    = sm + OSC;
    float* sbeta = sm + OBETA;
    float* smax_ = sm + OMAX;
    float* ssum_ = sm + OSUM;
    float* sf    = sm + OSF;
    float* spart = sm + OPART;
    float* syown = sm + OYOWN;
    float* syq   = sm + OYQ;
    float* sout  = sm + OOUT;

    const int tid = threadIdx.x;
    uint32_t rank;
    asm("mov.u32 %0, %%cluster_ctarank;" : "=r"(rank));
    const int r = (int)rank;
    const int b = blockIdx.x >> 2;

    // ---- phase 0 (overlaps k_pre under PDL): x tile [t][d] + xs partial ----
    if (tid < 64) sWs[tid] = Ws[r * 64 + tid];
    __syncthreads();
    {
        const int d = tid & 127, tg = tid >> 7;
        const float* xb = x + ((size_t)(b * TT + r * 64)) * DD + d;
        float acc = 0.f;
        #pragma unroll
        for (int k = 0; k < 32; k++) {
            int t = k * 2 + tg;
            float v = xb[t * DD];
            sx[t * SX_PAD + d] = v;
            acc += sWs[t] * v;
        }
        spart[tg * 128 + d] = acc;
    }
    __syncthreads();
    if (tid < 128) xs_p[tid] = spart[tid] + spart[128 + tid];
    CLUSTER_SYNC();   // #1 (no k_pre dependency yet)

    // ---- xs full across ranks (still independent of k_pre) ----
    if (tid < 128) {
        uint32_t la = smem_u32(xs_p + tid);
        float v = 0.f;
        #pragma unroll
        for (int rr = 0; rr < 4; rr++) v += ld_dsmem(mapa_rank(la, rr));
        xs_f[tid] = v;
    }
    __syncthreads();

    // first use of k_pre outputs below — wait for its grid now
    cudaGridDependencySynchronize();

    // ---- phase 1: u own d-quarter (float4 G loads), c[h] ----
    {   // u: thread (h = tid>>5; lane: strip = lane>>3 of 4, f4 = lane&7)
        const int h = tid >> 5, lane = tid & 31;
        const int strip = lane >> 3, f4 = lane & 7;
        const float4* G4 = (const float4*)g_G + h * 4096 + r * 8 + f4;
        float4 acc = make_float4(0.f, 0.f, 0.f, 0.f);
        #pragma unroll
        for (int i = 0; i < 32; i++) {
            int dp = strip * 32 + i;
            float xv = xs_f[dp];
            float4 gv = G4[dp * 32];
            acc.x += xv * gv.x; acc.y += xv * gv.y;
            acc.z += xv * gv.z; acc.w += xv * gv.w;
        }
        ((float4*)spart)[(h * 8 + f4) * 4 + strip] = acc;
    }
    __syncthreads();
    {   // reduce strips -> su[d*8+h] (+ S*ub)
        const int h = tid >> 5, f4 = (tid >> 2) & 7, comp = tid & 3;
        const int base = ((h * 8 + f4) * 4) * 4 + comp;
        float v = spart[base] + spart[base + 4] + spart[base + 8] + spart[base + 12];
        const int d = r * 32 + f4 * 4 + comp;
        su[d * 8 + h] = v + g_S * g_ub[h * 128 + d];
    }
    __syncthreads();
    CLUSTER_ARRIVE();   // #2 arrive — peers may read our su once they pass wait
    {   // c[h] computed in the barrier shadow (CTA-local)
        int h = tid >> 5, lane = tid & 31;
        float p = dot4(((const float4*)xs_f)[lane],
                       ((const float4*)g_gb)[h * 32 + lane]);
        #pragma unroll
        for (int o = 16; o > 0; o >>= 1)
            p += __shfl_xor_sync(0xffffffffu, p, o);
        if (lane == 0) sc[h] = p + g_S * g_dqs[h] + bs[0];
    }
    CLUSTER_WAIT();     // #2 wait

    // ---- phase 2: gather peers' u quarters; summary over own t-quarter ----
    #pragma unroll
    for (int j = 0; j < 3; j++) {
        int idx = j * 256 + tid;          // 0..767
        int ro = idx >> 8;                // 0..2
        int rr = ro + (ro >= r ? 1 : 0);  // skip own rank
        int off = rr * 256 + (idx & 255); // su offset = d*8+h, d in rr-quarter
        su[off] = ld_dsmem(mapa_rank(smem_u32(su + off), rr));
    }
    __syncthreads();
    {   // thread = (t = tid&63, dq = tid>>6 of 4): x row cached in registers
        const int t = tid & 63, dq = tid >> 6;
        float xr[32];
        const float4* xrow = (const float4*)(sx + t * SX_PAD + dq * 32);
        #pragma unroll
        for (int i = 0; i < 8; i++) {
            float4 v = xrow[i];
            xr[i * 4 + 0] = v.x; xr[i * 4 + 1] = v.y;
            xr[i * 4 + 2] = v.z; xr[i * 4 + 3] = v.w;
        }
        unsigned long long a0 = 0, a1 = 0, a2 = 0, a3 = 0;
        #pragma unroll
        for (int i = 0; i < 32; i++) {
            int d = dq * 32 + i;
            unsigned long long xp = pk2(xr[i], xr[i]);
            const unsigned long long* up = (const unsigned long long*)(su + d * 8);
            ffma2(a0, up[0], xp); ffma2(a1, up[1], xp);
            ffma2(a2, up[2], xp); ffma2(a3, up[3], xp);
        }
        float2 f0 = upk2(a0), f1 = upk2(a1), f2 = upk2(a2), f3 = upk2(a3);
        ((float4*)spart)[(t * 4 + dq) * 2 + 0] = make_float4(f0.x, f0.y, f1.x, f1.y);
        ((float4*)spart)[(t * 4 + dq) * 2 + 1] = make_float4(f2.x, f2.y, f3.x, f3.y);
    }
    __syncthreads();
    #pragma unroll
    for (int k = 0; k < 2; k++) {
        int i = tid + k * 256;            // i = t*8 + h
        int t = i >> 3, h = i & 7;
        sbeta[i] = spart[(t * 4 + 0) * 8 + h] + spart[(t * 4 + 1) * 8 + h]
                 + spart[(t * 4 + 2) * 8 + h] + spart[(t * 4 + 3) * 8 + h] + sc[h];
    }
    __syncthreads();

    // ---- phase 3: own-quarter softmax stats; sbeta <- e^{v-m_own} ----
    {
        int h = tid >> 5, lane = tid & 31;
        float v0 = sbeta[lane * 8 + h];
        float v1 = sbeta[(lane + 32) * 8 + h];
        float m = fmaxf(v0, v1);
        #pragma unroll
        for (int o = 16; o > 0; o >>= 1)
            m = fmaxf(m, __shfl_xor_sync(0xffffffffu, m, o));
        float e0 = __expf(v0 - m), e1 = __expf(v1 - m);
        float ss = e0 + e1;
        #pragma unroll
        for (int o = 16; o > 0; o >>= 1)
            ss += __shfl_xor_sync(0xffffffffu, ss, o);
        sbeta[lane * 8 + h] = e0;
        sbeta[(lane + 32) * 8 + h] = e1;
        if (lane == 0) { smax_[h] = m; ssum_[h] = ss; }
    }
    CLUSTER_SYNC();   // #3
    if (tid < 8) {
        float mo = smax_[tid];
        float M = mo, sums[4], maxs[4];
        #pragma unroll
        for (int rr = 0; rr < 4; rr++) {
            maxs[rr] = ld_dsmem(mapa_rank(smem_u32(smax_ + tid), rr));
            sums[rr] = ld_dsmem(mapa_rank(smem_u32(ssum_ + tid), rr));
            M = fmaxf(M, maxs[rr]);
        }
        float denom = 0.f;
        #pragma unroll
        for (int rr = 0; rr < 4; rr++) denom += sums[rr] * __expf(maxs[rr] - M);
        sf[tid] = __expf(mo - M) / denom;
    }
    __syncthreads();

    // ---- phase 4: y own t-quarter partial (renorm via sf) ----
    {
        const int d = tid & 127, tg = tid >> 7;
        unsigned long long a0 = 0, a1 = 0, a2 = 0, a3 = 0;
        #pragma unroll 8
        for (int t = tg * 32; t < tg * 32 + 32; t++) {
            float xv = sx[t * SX_PAD + d];
            unsigned long long xp = pk2(xv, xv);
            const ulonglong2* bp = (const ulonglong2*)(sbeta + t * 8);
            ulonglong2 b01 = bp[0], b23 = bp[1];
            ffma2(a0, b01.x, xp); ffma2(a1, b01.y, xp);
            ffma2(a2, b23.x, xp); ffma2(a3, b23.y, xp);
        }
        float2 v0 = upk2(a0), v1 = upk2(a1), v2 = upk2(a2), v3 = upk2(a3);
        float* pg = spart + tg * 1024;
        pg[0 * 128 + d] = v0.x; pg[1 * 128 + d] = v0.y;
        pg[2 * 128 + d] = v1.x; pg[3 * 128 + d] = v1.y;
        pg[4 * 128 + d] = v2.x; pg[5 * 128 + d] = v2.y;
        pg[6 * 128 + d] = v3.x; pg[7 * 128 + d] = v3.y;
    }
    __syncthreads();
    #pragma unroll
    for (int k = 0; k < 4; k++) {
        int i = tid + k * 256;            // i = k-index = h*128 + d
        syown[i] = sf[i >> 7] * (spart[i] + spart[1024 + i]);
    }
    CLUSTER_SYNC();   // #4

    // ---- phase 5: y full for own k-quarter; out partial (float4 M loads) ----
    {
        int k = r * 256 + tid;
        uint32_t la = smem_u32(syown + k);
        float v = 0.f;
        #pragma unroll
        for (int rr = 0; rr < 4; rr++) v += ld_dsmem(mapa_rank(la, rr));
        syq[tid] = v;
    }
    __syncthreads();
    {
        const int kg = tid >> 5, lane = tid & 31;
        const float4* M4 = (const float4*)g_M + (r * 256 + kg * 32) * 32 + lane;
        float4 acc = make_float4(0.f, 0.f, 0.f, 0.f);
        #pragma unroll
        for (int kk = 0; kk < 32; kk++) {
            float yk = syq[kg * 32 + kk];
            float4 mv = M4[kk * 32];
            acc.x += yk * mv.x; acc.y += yk * mv.y;
            acc.z += yk * mv.z; acc.w += yk * mv.w;
        }
        ((float4*)spart)[kg * 32 + lane] = acc;
    }
    __syncthreads();
    if (tid < 128) {
        float v = 0.f;
        #pragma unroll
        for (int kg = 0; kg < 8; kg++) v += spart[kg * 128 + tid];
        sout[tid] = v;
    }
    CLUSTER_SYNC();   // #5
    if (tid < 32) {
        int d2 = r * 32 + tid;
        float o = 0.f;
        #pragma unroll
        for (int p = 0; p < 8; p++) o += g_cbp[p * DD + d2];
        uint32_t la = smem_u32(sout + d2);
        #pragma unroll
        for (int rr = 0; rr < 4; rr++) o += ld_dsmem(mapa_rank(la, rr));
        out[b * DD + d2] = o;
    }
    CLUSTER_SYNC();   // #6: no CTA exits while peers may read its smem
}

// ===========================================================================
extern "C" void kernel_launch(void* const* d_in, const int* in_sizes, int n_in,
                              void* d_out, int out_size) {
    const float* x  = (const float*)d_in[0];
    const float* Wq = (const float*)d_in[1];
    const float* bq = (const float*)d_in[2];
    const float* Wk = (const float*)d_in[3];
    const float* bk = (const float*)d_in[4];
    const float* Wv = (const float*)d_in[5];
    const float* bv = (const float*)d_in[6];
    const float* Ws = (const float*)d_in[7];
    const float* bs = (const float*)d_in[8];
    const float* Wo = (const float*)d_in[9];
    const float* bo = (const float*)d_in[10];
    float* out = (float*)d_out;

    static bool attr_done = false;
    if (!attr_done) {
        cudaFuncSetAttribute(k_main, cudaFuncAttributeMaxDynamicSharedMemorySize,
                             K2_FLOATS * 4);
        attr_done = true;
    }

    k_pre<<<145, 256>>>(Ws, Wk, bk, Wq, bq, Wv, bv, Wo, bo);

    // k_main with PDL: k_pre triggers launch-completion at entry, so k_main's
    // phase 0 (x fill + xs) overlaps k_pre; gridDepSync gates first G/S use.
    cudaLaunchConfig_t cfg = {};
    cfg.gridDim = dim3(256, 1, 1);
    cfg.blockDim = dim3(256, 1, 1);
    cfg.dynamicSmemBytes = K2_FLOATS * 4;
    cfg.stream = 0;
    cudaLaunchAttribute attrs[2];
    attrs[0].id = cudaLaunchAttributeProgrammaticStreamSerialization;
    attrs[0].val.programmaticStreamSerializationAllowed = 1;
    attrs[1].id = cudaLaunchAttributeClusterDimension;
    attrs[1].val.clusterDim = {4, 1, 1};
    cfg.attrs = attrs;
    cfg.numAttrs = 2;
    cudaLaunchKernelEx(&cfg, k_main, x, Ws, bs, out);
}